// round 10
// baseline (speedup 1.0000x reference)
#include <cuda_runtime.h>
#include <math.h>
#include <stdint.h>

#define NIMG   8
#define KSEL   4768
#define NWORDS 75          /* ceil(4768/64) */
#define POSTN  1000
#define CANDCAP 16384

typedef unsigned long long u64;
typedef unsigned int u32;

__device__ __constant__ int c_FEAT[5]   = {256, 128, 64, 32, 16};
__device__ __constant__ int c_KLVL[5]   = {1000, 1000, 1000, 1000, 768};
__device__ __constant__ int c_SELOFF[5] = {0, 1000, 2000, 3000, 4000};
__device__ __constant__ int c_LOFF[5]   = {0, 196608, 245760, 258048, 261120};

struct KArgs {
    const float* obj[5];
    const float* del[5];
    const float* anc;
};

// ------------- static device scratch (no allocation) -------------
__device__ u32    g_hist[40][256];             // global radix histograms (re-zeroed by cut)
__device__ u32    g_d1[40], g_kr0[40], g_cntC[40];
__device__ u32    g_selIdx[NIMG][KSEL];        // concat-pos -> global anchor index
__device__ u64    g_cand[40][CANDCAP];         // sel candidate scratch
__device__ u64    g_key[NIMG][KSEL];           // composite sort keys (pos-indexed)
__device__ float4 g_px[NIMG][KSEL];            // pos-indexed clipped boxes
__device__ float  g_sx1[NIMG][KSEL], g_sy1[NIMG][KSEL], g_sx2[NIMG][KSEL], g_sy2[NIMG][KSEL];
__device__ float  g_ox1[NIMG][KSEL], g_oy1[NIMG][KSEL], g_ox2[NIMG][KSEL], g_oy2[NIMG][KSEL];
__device__ float  g_area[NIMG][KSEL];
__device__ unsigned char g_slvl[NIMG][KSEL];   // level per sorted rank
__device__ u64    g_vbits[NIMG][NWORDS];       // per-chunk valid bitmask (rank order)
__device__ u64    g_mask[NIMG][KSEL][NWORDS];  // suppression bit matrix (upper tri only)

// monotone float->uint key (ascending float == ascending uint)
__device__ __forceinline__ u32 fkey(float f) {
    u32 b = __float_as_uint(f);
    return (b & 0x80000000u) ? ~b : (b | 0x80000000u);
}

// ================= sel stage A: chip-wide top-8-bit histogram =================
__global__ __launch_bounds__(256) void histA_kernel(KArgs A) {
    int pair = blockIdx.x; int img = pair / 5, lvl = pair % 5;
    int F = c_FEAT[lvl]; int HW = F * F; int n = HW * 3;
    const float* base = A.obj[lvl] + (size_t)img * 3 * HW;
    __shared__ u32 h[256];
    h[threadIdx.x] = 0;
    __syncthreads();
    int stride = gridDim.y * 256;
    for (int t = blockIdx.y * 256 + threadIdx.x; t < n; t += stride)
        atomicAdd(&h[fkey(base[t]) >> 24], 1u);
    __syncthreads();
    u32 v = h[threadIdx.x];
    if (v) atomicAdd(&g_hist[pair][threadIdx.x], v);
}

// ================= sel stage B: find cut bucket (and re-zero state) =================
__global__ __launch_bounds__(256) void cut_kernel() {
    int pair = threadIdx.x;
    if (pair < 40) {
        int lvl = pair % 5;
        u32 kr = (u32)c_KLVL[lvl], sum = 0; int d = 0;
        for (d = 255; d >= 0; d--) {
            u32 s2 = sum + g_hist[pair][d];
            if (s2 >= kr) { g_kr0[pair] = kr - sum; break; }
            sum = s2;
        }
        g_d1[pair] = (u32)d;
        g_cntC[pair] = 0;
    }
    __syncthreads();
    // re-zero histograms for the next graph replay (deterministic invariant)
    for (int t = threadIdx.x; t < 40 * 256; t += 256)
        ((u32*)g_hist)[t] = 0;
}

// ================= sel stage C: chip-wide candidate compaction =================
__global__ __launch_bounds__(256) void compact_kernel(KArgs A) {
    int pair = blockIdx.x; int img = pair / 5, lvl = pair % 5;
    int F = c_FEAT[lvl]; int HW = F * F; int n = HW * 3;
    const float* base = A.obj[lvl] + (size_t)img * 3 * HW;
    u32 d1 = g_d1[pair];
    u64* cand = g_cand[pair];
    int stride = gridDim.y * 256;
    for (int t = blockIdx.y * 256 + threadIdx.x; t < n; t += stride) {
        u32 key = fkey(base[t]);
        if ((key >> 24) >= d1) {
            u32 s = atomicAdd(&g_cntC[pair], 1u);
            if (s < CANDCAP) {
                int a = t / HW; int hw = t - a * HW;
                u32 local = (u32)hw * 3u + (u32)a;     // [H,W,A] flatten index
                cand[s] = ((u64)key << 32) | (u32)(~local);
            }
        }
    }
}

// ================= sel stage D: radix passes 3-5 + tie sort on candidates =================
__global__ __launch_bounds__(1024) void selfin_kernel() {
    int pair = blockIdx.x; int img = pair / 5, lvl = pair % 5;
    int k = c_KLVL[lvl];
    u64* cand = g_cand[pair];
    u32 m = g_cntC[pair]; if (m > CANDCAP) m = CANDCAP;

    __shared__ u32 hist[256];
    __shared__ u32 sh_prefix, sh_kr;
    __shared__ u64 buf[2048];
    __shared__ u32 cntG, cntE;
    if (threadIdx.x == 0) {
        sh_prefix = g_d1[pair] << 24; sh_kr = g_kr0[pair];
        cntG = 0; cntE = 0;
    }
    __syncthreads();

    for (int b = 2; b >= 0; b--) {
        for (int t = threadIdx.x; t < 256; t += blockDim.x) hist[t] = 0;
        __syncthreads();
        u32 pref = sh_prefix;
        u32 maskH = 0xFFFFFFFFu << (8 * (b + 1));
        for (int t = threadIdx.x; t < (int)m; t += blockDim.x) {
            u32 key = (u32)(cand[t] >> 32);
            if ((key & maskH) == (pref & maskH))
                atomicAdd(&hist[(key >> (8 * b)) & 255u], 1u);
        }
        __syncthreads();
        if (threadIdx.x == 0) {
            u32 kr = sh_kr, sum = 0; int d = 0;
            for (d = 255; d >= 0; d--) {
                u32 s2 = sum + hist[d];
                if (s2 >= kr) { sh_kr = kr - sum; break; }
                sum = s2;
            }
            sh_prefix = pref | ((u32)d << (8 * b));
        }
        __syncthreads();
    }
    u32 Kth = sh_prefix;

    for (int t = threadIdx.x; t < 2048; t += blockDim.x) buf[t] = 0ull;
    __syncthreads();
    for (int t = threadIdx.x; t < (int)m; t += blockDim.x) {
        u64 comp = cand[t];
        u32 key = (u32)(comp >> 32);
        if (key > Kth)       { u32 s = atomicAdd(&cntG, 1u); if (s < 1000u) buf[s] = comp; }
        else if (key == Kth) { u32 s = atomicAdd(&cntE, 1u); if (s < 1048u) buf[1000u + s] = comp; }
    }
    __syncthreads();

    // bitonic sort 2048 descending on (key desc, local asc)
    for (int kk = 2; kk <= 2048; kk <<= 1)
        for (int j = kk >> 1; j > 0; j >>= 1) {
            __syncthreads();
            for (int t = threadIdx.x; t < 2048; t += blockDim.x) {
                int ixj = t ^ j;
                if (ixj > t) {
                    u64 a = buf[t], bb = buf[ixj];
                    bool desc = ((t & kk) == 0);
                    if (desc ? (a < bb) : (a > bb)) { buf[t] = bb; buf[ixj] = a; }
                }
            }
        }
    __syncthreads();

    int seloff = c_SELOFF[lvl], loff = c_LOFF[lvl];
    for (int r = threadIdx.x; r < k; r += blockDim.x) {
        u32 local = ~(u32)buf[r];
        g_selIdx[img][seloff + r] = (u32)loff + local;
    }
}

// ================= decode: chip-wide box decode + key build =================
__global__ __launch_bounds__(256) void decode_kernel(KArgs A) {
    int img = blockIdx.y;
    int p = blockIdx.x * 256 + threadIdx.x;
    if (p >= KSEL) return;
    int lvl = p / 1000; if (lvl > 4) lvl = 4;
    u32 gidx = g_selIdx[img][p];
    int loff = c_LOFF[lvl]; int F = c_FEAT[lvl]; int HW = F * F;
    u32 local = gidx - (u32)loff;
    int a = (int)(local % 3u); int hw = (int)(local / 3u);
    int h = hw / F; int w = hw - h * F;

    float logit = A.obj[lvl][((size_t)img * 3 + a) * HW + hw];
    float score = __fdiv_rn(1.0f, __fadd_rn(1.0f, expf(-logit)));

    const float* dp = A.del[lvl] + ((size_t)img * 12 + a * 4) * HW + (size_t)h * F + w;
    float dx  = dp[0];
    float dy  = dp[(size_t)HW];
    float dwv = dp[2 * (size_t)HW];
    float dhv = dp[3 * (size_t)HW];
    const float* an = A.anc + 4 * (size_t)gidx;
    float ax1 = an[0], ay1 = an[1], ax2 = an[2], ay2 = an[3];
    float aw = __fsub_rn(ax2, ax1);
    float ah = __fsub_rn(ay2, ay1);
    float cx = __fadd_rn(ax1, __fmul_rn(0.5f, aw));
    float cy = __fadd_rn(ay1, __fmul_rn(0.5f, ah));
    const float CLIP = 4.135166556742356f;
    float dwc = fminf(dwv, CLIP);
    float dhc = fminf(dhv, CLIP);
    float pcx = __fadd_rn(__fmul_rn(dx, aw), cx);
    float pcy = __fadd_rn(__fmul_rn(dy, ah), cy);
    float pw  = __fmul_rn(expf(dwc), aw);
    float ph  = __fmul_rn(expf(dhc), ah);
    float x1 = __fsub_rn(pcx, __fmul_rn(0.5f, pw));
    float y1 = __fsub_rn(pcy, __fmul_rn(0.5f, ph));
    float x2 = __fadd_rn(pcx, __fmul_rn(0.5f, pw));
    float y2 = __fadd_rn(pcy, __fmul_rn(0.5f, ph));
    x1 = fminf(fmaxf(x1, 0.0f), 1024.0f);
    y1 = fminf(fmaxf(y1, 0.0f), 1024.0f);
    x2 = fminf(fmaxf(x2, 0.0f), 1024.0f);
    y2 = fminf(fmaxf(y2, 0.0f), 1024.0f);

    bool valid = (__fsub_rn(x2, x1) >= 1e-3f) && (__fsub_rn(y2, y1) >= 1e-3f);
    g_px[img][p] = make_float4(x1, y1, x2, y2);
    float sc = valid ? score : -1.0f;
    g_key[img][p] = ((u64)fkey(sc) << 32) | (u32)(~(u32)p);
}

// ================= rank: merge-rank + scatter (per image) =================
__global__ __launch_bounds__(1024) void rank_kernel() {
    int img = blockIdx.x;
    int tid = threadIdx.x;
    int lane = tid & 31, warp = tid >> 5;

    __shared__ u64 levKeys[KSEL];
    __shared__ u32 sh_wsum[32];
    __shared__ u32 sh_levStart[6];
    __shared__ u32 sh_carry, sh_total;

    for (int t = tid; t < NWORDS; t += 1024) g_vbits[img][t] = 0ull;

    u64 key[5]; u32 gvp[5]; bool val[5];
    #pragma unroll
    for (int s = 0; s < 5; s++) {
        int p = s * 1024 + tid;
        key[s] = 0ull; val[s] = false;
        if (p < KSEL) {
            u64 kk = g_key[img][p];
            key[s] = kk;
            val[s] = ((u32)(kk >> 32)) >= 0x80000000u;   // sigmoid>0 vs -1
        }
    }
    if (tid == 0) sh_carry = 0;

    // block-wide exclusive scan of valid flags (pos order)
    #pragma unroll
    for (int s = 0; s < 5; s++) {
        int p = s * 1024 + tid;
        u32 bal = __ballot_sync(0xFFFFFFFFu, val[s]);
        u32 wpre = __popc(bal & ((1u << lane) - 1u));
        __syncthreads();
        if (lane == 0) sh_wsum[warp] = __popc(bal);
        __syncthreads();
        if (tid < 32) {
            u32 v = sh_wsum[tid];
            u32 x = v;
            #pragma unroll
            for (int o = 1; o < 32; o <<= 1) {
                u32 y = __shfl_up_sync(0xFFFFFFFFu, x, o);
                if (tid >= o) x += y;
            }
            sh_wsum[tid] = x - v;
            if (tid == 31) sh_total = x;
        }
        __syncthreads();
        gvp[s] = sh_carry + sh_wsum[warp] + wpre;
        if (p < KSEL && (p % 1000) == 0 && p < 5000) sh_levStart[p / 1000] = gvp[s];
        __syncthreads();
        if (tid == 0) sh_carry += sh_total;
    }
    __syncthreads();
    if (tid == 0) sh_levStart[5] = sh_carry;
    __syncthreads();

    #pragma unroll
    for (int s = 0; s < 5; s++) {
        int p = s * 1024 + tid;
        if (p < KSEL && val[s]) levKeys[gvp[s]] = key[s];
    }
    __syncthreads();
    u32 totalValid = sh_levStart[5];

    #pragma unroll
    for (int s = 0; s < 5; s++) {
        int p = s * 1024 + tid;
        if (p >= KSEL) continue;
        int lvl = p / 1000; if (lvl > 4) lvl = 4;
        u32 r;
        if (val[s]) {
            r = gvp[s] - sh_levStart[lvl];
            #pragma unroll
            for (int l2 = 0; l2 < 5; l2++) {
                if (l2 == lvl) continue;
                u32 lo = sh_levStart[l2], hi = sh_levStart[l2 + 1];
                u32 st = lo;
                while (lo < hi) {
                    u32 mid = (lo + hi) >> 1;
                    if (levKeys[mid] > key[s]) lo = mid + 1; else hi = mid;
                }
                r += lo - st;
            }
        } else {
            r = totalValid + ((u32)p - gvp[s]);
        }
        float4 b = g_px[img][p];
        g_sx1[img][r] = b.x; g_sy1[img][r] = b.y; g_sx2[img][r] = b.z; g_sy2[img][r] = b.w;
        float ofs = (float)lvl * 1025.0f;
        float ox1 = __fadd_rn(b.x, ofs), oy1 = __fadd_rn(b.y, ofs);
        float ox2 = __fadd_rn(b.z, ofs), oy2 = __fadd_rn(b.w, ofs);
        g_ox1[img][r] = ox1; g_oy1[img][r] = oy1; g_ox2[img][r] = ox2; g_oy2[img][r] = oy2;
        g_area[img][r] = __fmul_rn(__fsub_rn(ox2, ox1), __fsub_rn(oy2, oy1));
        g_slvl[img][r] = (unsigned char)lvl;
        if (val[s]) atomicOr(&g_vbits[img][r >> 6], 1ull << (r & 63));
    }
}

// ================= mask: IoU suppression matrix (upper tri, level-gated) =================
__global__ __launch_bounds__(256) void mask_kernel() {
    int colb = blockIdx.x, rowb4 = blockIdx.y, img = blockIdx.z;
    if (rowb4 * 4 > colb) return;
    int tid = threadIdx.x;
    int sub = tid >> 6;
    int lane64 = tid & 63;
    int rowb = rowb4 * 4 + sub;

    __shared__ float cx1[64], cy1[64], cx2[64], cy2[64], car[64];
    __shared__ u64 lvlbits[5];
    if (tid < 5) lvlbits[tid] = 0ull;
    __syncthreads();
    int j0 = colb * 64;
    if (tid < 64) {
        int tj = j0 + tid;
        if (tj < KSEL) {
            cx1[tid] = g_ox1[img][tj]; cy1[tid] = g_oy1[img][tj];
            cx2[tid] = g_ox2[img][tj]; cy2[tid] = g_oy2[img][tj];
            car[tid] = g_area[img][tj];
            atomicOr(&lvlbits[g_slvl[img][tj]], 1ull << tid);
        }
    }
    __syncthreads();
    if (rowb > colb) return;
    int i = rowb * 64 + lane64;
    if (i >= KSEL) return;
    int myl = (int)g_slvl[img][i];
    float ix1 = g_ox1[img][i], iy1 = g_oy1[img][i];
    float ix2 = g_ox2[img][i], iy2 = g_oy2[img][i];
    float ai = g_area[img][i];
    u64 candm = lvlbits[myl];
    if (rowb == colb) {
        int sh = i - j0;
        u64 low = (sh == 63) ? ~0ull : ((1ull << (sh + 1)) - 1ull);
        candm &= ~low;
    }
    u64 word = 0ull;
    while (candm) {
        int jj = __ffsll((long long)candm) - 1;
        candm &= candm - 1ull;
        float ltx = fmaxf(ix1, cx1[jj]);
        float lty = fmaxf(iy1, cy1[jj]);
        float rbx = fminf(ix2, cx2[jj]);
        float rby = fminf(iy2, cy2[jj]);
        float w = fmaxf(__fsub_rn(rbx, ltx), 0.0f);
        float h = fmaxf(__fsub_rn(rby, lty), 0.0f);
        float inter = __fmul_rn(w, h);
        float den = __fadd_rn(__fsub_rn(__fadd_rn(ai, car[jj]), inter), 1e-9f);
        if (__fdiv_rn(inter, den) > 0.7f) word |= (1ull << jj);
    }
    g_mask[img][i][colb] = word;
}

// ================= nms: pipelined greedy scan =================
// Invariant: before walking chunk c, remv[c] contains OR of mask[r][c] for all
// rows r kept in chunks < c. Rows kept in chunk c-1 contribute via the pre[]
// fixup (loaded during walk c-1, zero global latency on chain); rows kept in
// chunks <= c-2 via eager ORs done concurrently with walk c-1.
__global__ __launch_bounds__(256) void nms_kernel(float* __restrict__ out) {
    int img = blockIdx.x;
    int tid = threadIdx.x;
    __shared__ u64 remv[NWORDS];
    __shared__ u64 svb[NWORDS];
    __shared__ u64 smask[2][64];
    __shared__ u64 pre[64];
    __shared__ int skept[2][64];
    __shared__ u64 skeptMask;
    __shared__ int snk[2];
    __shared__ int skbase;

    for (int t = tid; t < NWORDS; t += 256) { remv[t] = 0ull; svb[t] = g_vbits[img][t]; }
    if (tid < 64) smask[0][tid] = g_mask[img][tid][0];
    if (tid == 0) { skbase = 0; snk[0] = 0; snk[1] = 0; skeptMask = 0ull; }
    __syncthreads();

    for (int c = 0; c < NWORDS; c++) {
        if (skbase >= POSTN) break;              // uniform (shared, synced)
        int par = c & 1;
        int i0 = c * 64;
        if (tid == 0) {
            // serial greedy walk of chunk c
            u64 alive = svb[c] & ~remv[c];
            int nk = 0; u64 km = 0ull;
            while (alive) {
                int b = __ffsll((long long)alive) - 1;
                skept[par][nk] = i0 + b; km |= (1ull << b); nk++;
                alive &= ~smask[par][b];          // row has only j>i bits
                alive &= ~(1ull << b);
            }
            snk[par] = nk; skeptMask = km;
        } else {
            int c1 = c + 1;
            if (c1 < NWORDS) {
                if (tid >= 64 && tid < 128) {     // prefetch next diag words
                    int t = tid - 64; int i = c1 * 64 + t;
                    smask[par ^ 1][t] = (i < KSEL) ? g_mask[img][i][c1] : 0ull;
                }
                if (tid >= 128 && tid < 192) {    // prefetch chunk-c rows @ word c+1
                    int t = tid - 128; int i = i0 + t;
                    pre[t] = (i < KSEL) ? g_mask[img][i][c1] : 0ull;
                }
            }
            // eager: rows kept in chunk c-1 -> remv words >= c+1
            if (c > 0) {
                int pnk = snk[par ^ 1];
                int nw = NWORDS - 1 - c;
                int total = pnk * nw;
                for (int p = tid - 1; p < total; p += 255) {
                    int kk = p / nw; int w = c + 1 + (p - kk * nw);
                    u64 m = g_mask[img][skept[par ^ 1][kk]][w];
                    if (m) atomicOr(&remv[w], m);
                }
            }
        }
        __syncthreads();
        int nk = snk[par], kb = skbase;
        // fixup remv[c+1] from prefetched pre[] (no global latency)
        if (c + 1 < NWORDS && tid < 64) {
            if ((skeptMask >> tid) & 1ull) {
                u64 m = pre[tid];
                if (m) atomicOr(&remv[c + 1], m);
            }
        }
        // write kept boxes
        for (int kk = tid; kk < nk; kk += 256) {
            int rank = kb + kk;
            if (rank < POSTN) {
                int i = skept[par][kk];
                float* o = out + ((size_t)img * POSTN + rank) * 4;
                o[0] = g_sx1[img][i]; o[1] = g_sy1[img][i];
                o[2] = g_sx2[img][i]; o[3] = g_sy2[img][i];
            }
        }
        if (tid == 0) skbase = kb + nk;
        __syncthreads();
    }
    __syncthreads();
    int tot = skbase; if (tot > POSTN) tot = POSTN;
    for (int idx = tot * 4 + tid; idx < POSTN * 4; idx += 256)
        out[(size_t)img * POSTN * 4 + idx] = 0.0f;
}

// ================= host launcher =================
extern "C" void kernel_launch(void* const* d_in, const int* in_sizes, int n_in,
                              void* d_out, int out_size) {
    KArgs A;
    bool interleaved = (in_sizes[1] == 6291456);
    for (int i = 0; i < 5; i++) {
        A.obj[i] = (const float*)d_in[interleaved ? 2 * i : i];
        A.del[i] = (const float*)d_in[interleaved ? 2 * i + 1 : 5 + i];
    }
    A.anc = (const float*)d_in[10];
    float* out = (float*)d_out;

    histA_kernel<<<dim3(40, 16), 256>>>(A);
    cut_kernel<<<1, 256>>>();
    compact_kernel<<<dim3(40, 16), 256>>>(A);
    selfin_kernel<<<40, 1024>>>();
    decode_kernel<<<dim3(19, NIMG), 256>>>(A);
    rank_kernel<<<NIMG, 1024>>>();
    mask_kernel<<<dim3(NWORDS, 19, NIMG), 256>>>();
    nms_kernel<<<NIMG, 256>>>(out);
}

// round 11
// speedup vs baseline: 1.4738x; 1.4738x over previous
#include <cuda_runtime.h>
#include <math.h>
#include <stdint.h>

#define NIMG   8
#define KSEL   4768
#define NWORDS 75          /* ceil(4768/64) global-rank words */
#define NWL    16          /* per-level mask words (1024/64) */
#define POSTN  1000
#define CANDCAP 16384

typedef unsigned long long u64;
typedef unsigned int u32;

__device__ __constant__ int c_FEAT[5]   = {256, 128, 64, 32, 16};
__device__ __constant__ int c_KLVL[5]   = {1000, 1000, 1000, 1000, 768};
__device__ __constant__ int c_SELOFF[5] = {0, 1000, 2000, 3000, 4000};
__device__ __constant__ int c_LOFF[5]   = {0, 196608, 245760, 258048, 261120};

struct KArgs {
    const float* obj[5];
    const float* del[5];
    const float* anc;
};

// ------------- static device scratch (no allocation) -------------
__device__ u32    g_hist[40][256];             // radix histograms (re-zeroed by cut)
__device__ u32    g_d1[40], g_kr0[40], g_cntC[40];
__device__ u32    g_selIdx[NIMG][KSEL];        // concat-pos -> global anchor index
__device__ u64    g_cand[40][CANDCAP];         // sel candidate scratch
__device__ u64    g_key[NIMG][KSEL];           // composite sort keys (pos-indexed)
__device__ float4 g_px[NIMG][KSEL];            // pos-indexed clipped boxes
// per-(img,lvl) level-local offset boxes / area / validity / keep bits
__device__ float  g_lx1[40][1024], g_ly1[40][1024], g_lx2[40][1024], g_ly2[40][1024];
__device__ float  g_lar[40][1024];
__device__ u64    g_lvb[40][NWL];              // valid bits (zeroed by cut)
__device__ u64    g_keepbits[40][NWL];         // NMS keep flags per level
__device__ u64    g_lmask[40][1024][NWL];      // per-level suppression matrix

// monotone float->uint key (ascending float == ascending uint)
__device__ __forceinline__ u32 fkey(float f) {
    u32 b = __float_as_uint(f);
    return (b & 0x80000000u) ? ~b : (b | 0x80000000u);
}

// ================= sel stage A: chip-wide top-8-bit histogram =================
__global__ __launch_bounds__(256) void histA_kernel(KArgs A) {
    int pair = blockIdx.x; int img = pair / 5, lvl = pair % 5;
    int F = c_FEAT[lvl]; int HW = F * F; int n = HW * 3;
    const float* base = A.obj[lvl] + (size_t)img * 3 * HW;
    __shared__ u32 h[256];
    h[threadIdx.x] = 0;
    __syncthreads();
    int stride = gridDim.y * 256;
    for (int t = blockIdx.y * 256 + threadIdx.x; t < n; t += stride)
        atomicAdd(&h[fkey(base[t]) >> 24], 1u);
    __syncthreads();
    u32 v = h[threadIdx.x];
    if (v) atomicAdd(&g_hist[pair][threadIdx.x], v);
}

// ================= sel stage B: find cut bucket + re-zero per-replay state =================
__global__ __launch_bounds__(256) void cut_kernel() {
    int pair = threadIdx.x;
    if (pair < 40) {
        int lvl = pair % 5;
        u32 kr = (u32)c_KLVL[lvl], sum = 0; int d = 0;
        for (d = 255; d >= 0; d--) {
            u32 s2 = sum + g_hist[pair][d];
            if (s2 >= kr) { g_kr0[pair] = kr - sum; break; }
            sum = s2;
        }
        g_d1[pair] = (u32)d;
        g_cntC[pair] = 0;
    }
    __syncthreads();
    for (int t = threadIdx.x; t < 40 * 256; t += 256)
        ((u32*)g_hist)[t] = 0;                 // for next replay
    for (int t = threadIdx.x; t < 40 * NWL; t += 256)
        ((u64*)g_lvb)[t] = 0ull;               // decode atomicOrs into this
}

// ================= sel stage C: chip-wide candidate compaction =================
__global__ __launch_bounds__(256) void compact_kernel(KArgs A) {
    int pair = blockIdx.x; int img = pair / 5, lvl = pair % 5;
    int F = c_FEAT[lvl]; int HW = F * F; int n = HW * 3;
    const float* base = A.obj[lvl] + (size_t)img * 3 * HW;
    u32 d1 = g_d1[pair];
    u64* cand = g_cand[pair];
    int stride = gridDim.y * 256;
    for (int t = blockIdx.y * 256 + threadIdx.x; t < n; t += stride) {
        u32 key = fkey(base[t]);
        if ((key >> 24) >= d1) {
            u32 s = atomicAdd(&g_cntC[pair], 1u);
            if (s < CANDCAP) {
                int a = t / HW; int hw = t - a * HW;
                u32 local = (u32)hw * 3u + (u32)a;     // [H,W,A] flatten index
                cand[s] = ((u64)key << 32) | (u32)(~local);
            }
        }
    }
}

// ================= sel stage D: radix 3-5 + counting-rank (no bitonic) =================
__global__ __launch_bounds__(1024) void selfin_kernel() {
    int pair = blockIdx.x; int img = pair / 5, lvl = pair % 5;
    int k = c_KLVL[lvl];
    u64* cand = g_cand[pair];
    u32 m = g_cntC[pair]; if (m > CANDCAP) m = CANDCAP;

    __shared__ u32 hist[256];
    __shared__ u32 sh_prefix, sh_kr;
    __shared__ u64 buf[2048];
    __shared__ u32 cntG, cntE;
    if (threadIdx.x == 0) {
        sh_prefix = g_d1[pair] << 24; sh_kr = g_kr0[pair];
        cntG = 0; cntE = 0;
    }
    __syncthreads();

    for (int b = 2; b >= 0; b--) {
        for (int t = threadIdx.x; t < 256; t += blockDim.x) hist[t] = 0;
        __syncthreads();
        u32 pref = sh_prefix;
        u32 maskH = 0xFFFFFFFFu << (8 * (b + 1));
        for (int t = threadIdx.x; t < (int)m; t += blockDim.x) {
            u32 key = (u32)(cand[t] >> 32);
            if ((key & maskH) == (pref & maskH))
                atomicAdd(&hist[(key >> (8 * b)) & 255u], 1u);
        }
        __syncthreads();
        if (threadIdx.x == 0) {
            u32 kr = sh_kr, sum = 0; int d = 0;
            for (d = 255; d >= 0; d--) {
                u32 s2 = sum + hist[d];
                if (s2 >= kr) { sh_kr = kr - sum; break; }
                sum = s2;
            }
            sh_prefix = pref | ((u32)d << (8 * b));
        }
        __syncthreads();
    }
    u32 Kth = sh_prefix;

    for (int t = threadIdx.x; t < 2048; t += blockDim.x) buf[t] = 0ull;
    __syncthreads();
    for (int t = threadIdx.x; t < (int)m; t += blockDim.x) {
        u64 comp = cand[t];
        u32 key = (u32)(comp >> 32);
        if (key > Kth)       { u32 s = atomicAdd(&cntG, 1u); if (s < 1000u) buf[s] = comp; }
        else if (key == Kth) { u32 s = atomicAdd(&cntE, 1u); if (s < 1048u) buf[1000u + s] = comp; }
    }
    __syncthreads();

    // counting rank: keys are unique (distinct low bits); padding zeros rank last
    int nG = cntG < 1000u ? (int)cntG : 1000;
    int nE = cntE < 1048u ? (int)cntE : 1048;
    u64 e0 = buf[threadIdx.x], e1 = buf[threadIdx.x + 1024];
    int r0 = 0, r1 = 0;
    #pragma unroll 4
    for (int j = 0; j < nG; j++) {
        u64 v = buf[j];
        r0 += (v > e0); r1 += (v > e1);
    }
    #pragma unroll 4
    for (int j = 1000; j < 1000 + nE; j++) {
        u64 v = buf[j];
        r0 += (v > e0); r1 += (v > e1);
    }
    int seloff = c_SELOFF[lvl], loff = c_LOFF[lvl];
    if (e0 && r0 < k) g_selIdx[img][seloff + r0] = (u32)loff + (~(u32)e0);
    if (e1 && r1 < k) g_selIdx[img][seloff + r1] = (u32)loff + (~(u32)e1);
}

// ================= decode: boxes, keys, level-local offset boxes + valid bits ==========
__global__ __launch_bounds__(256) void decode_kernel(KArgs A) {
    int img = blockIdx.y;
    int p = blockIdx.x * 256 + threadIdx.x;
    if (p >= KSEL) return;
    int lvl = p / 1000; if (lvl > 4) lvl = 4;
    u32 gidx = g_selIdx[img][p];
    int loff = c_LOFF[lvl]; int F = c_FEAT[lvl]; int HW = F * F;
    u32 local = gidx - (u32)loff;
    int a = (int)(local % 3u); int hw = (int)(local / 3u);
    int h = hw / F; int w = hw - h * F;

    float logit = A.obj[lvl][((size_t)img * 3 + a) * HW + hw];
    float score = __fdiv_rn(1.0f, __fadd_rn(1.0f, expf(-logit)));

    const float* dp = A.del[lvl] + ((size_t)img * 12 + a * 4) * HW + (size_t)h * F + w;
    float dx  = dp[0];
    float dy  = dp[(size_t)HW];
    float dwv = dp[2 * (size_t)HW];
    float dhv = dp[3 * (size_t)HW];
    const float* an = A.anc + 4 * (size_t)gidx;
    float ax1 = an[0], ay1 = an[1], ax2 = an[2], ay2 = an[3];
    float aw = __fsub_rn(ax2, ax1);
    float ah = __fsub_rn(ay2, ay1);
    float cx = __fadd_rn(ax1, __fmul_rn(0.5f, aw));
    float cy = __fadd_rn(ay1, __fmul_rn(0.5f, ah));
    const float CLIP = 4.135166556742356f;
    float dwc = fminf(dwv, CLIP);
    float dhc = fminf(dhv, CLIP);
    float pcx = __fadd_rn(__fmul_rn(dx, aw), cx);
    float pcy = __fadd_rn(__fmul_rn(dy, ah), cy);
    float pw  = __fmul_rn(expf(dwc), aw);
    float ph  = __fmul_rn(expf(dhc), ah);
    float x1 = __fsub_rn(pcx, __fmul_rn(0.5f, pw));
    float y1 = __fsub_rn(pcy, __fmul_rn(0.5f, ph));
    float x2 = __fadd_rn(pcx, __fmul_rn(0.5f, pw));
    float y2 = __fadd_rn(pcy, __fmul_rn(0.5f, ph));
    x1 = fminf(fmaxf(x1, 0.0f), 1024.0f);
    y1 = fminf(fmaxf(y1, 0.0f), 1024.0f);
    x2 = fminf(fmaxf(x2, 0.0f), 1024.0f);
    y2 = fminf(fmaxf(y2, 0.0f), 1024.0f);

    bool valid = (__fsub_rn(x2, x1) >= 1e-3f) && (__fsub_rn(y2, y1) >= 1e-3f);
    g_px[img][p] = make_float4(x1, y1, x2, y2);
    float sc = valid ? score : -1.0f;
    g_key[img][p] = ((u64)fkey(sc) << 32) | (u32)(~(u32)p);

    // level-local offset boxes (reference computes IoU on offset coords)
    int pair = img * 5 + lvl;
    int li = p - c_SELOFF[lvl];
    float ofs = (float)lvl * 1025.0f;
    float ox1 = __fadd_rn(x1, ofs), oy1 = __fadd_rn(y1, ofs);
    float ox2 = __fadd_rn(x2, ofs), oy2 = __fadd_rn(y2, ofs);
    g_lx1[pair][li] = ox1; g_ly1[pair][li] = oy1;
    g_lx2[pair][li] = ox2; g_ly2[pair][li] = oy2;
    g_lar[pair][li] = __fmul_rn(__fsub_rn(ox2, ox1), __fsub_rn(oy2, oy1));
    if (valid) atomicOr(&g_lvb[pair][li >> 6], 1ull << (li & 63));
}

// ================= per-level IoU suppression matrix (upper tri) =================
__global__ __launch_bounds__(256) void lmask_kernel() {
    int pair = blockIdx.z; int lvl = pair % 5;
    int kl = c_KLVL[lvl];
    int colb = blockIdx.x, rowb4 = blockIdx.y;
    if (rowb4 * 4 > colb) return;            // whole block lower triangle
    int tid = threadIdx.x;
    int sub = tid >> 6, lane = tid & 63;
    int rowb = rowb4 * 4 + sub;

    __shared__ float cx1[64], cy1[64], cx2[64], cy2[64], car[64];
    int j0 = colb * 64;
    if (tid < 64) {
        int j = j0 + tid;
        if (j < kl) {
            cx1[tid] = g_lx1[pair][j]; cy1[tid] = g_ly1[pair][j];
            cx2[tid] = g_lx2[pair][j]; cy2[tid] = g_ly2[pair][j];
            car[tid] = g_lar[pair][j];
        } else {
            cx1[tid] = 0.f; cy1[tid] = 0.f; cx2[tid] = 0.f; cy2[tid] = 0.f; car[tid] = 0.f;
        }
    }
    __syncthreads();
    if (rowb > colb) return;
    int i = rowb * 64 + lane;
    u64 word = 0ull;
    if (i < kl) {
        float ix1 = g_lx1[pair][i], iy1 = g_ly1[pair][i];
        float ix2 = g_lx2[pair][i], iy2 = g_ly2[pair][i];
        float ai = g_lar[pair][i];
        int jmax = kl - j0; if (jmax > 64) jmax = 64;
        #pragma unroll 8
        for (int jj = 0; jj < 64; jj++) {
            if (jj < jmax && j0 + jj > i) {
                float ltx = fmaxf(ix1, cx1[jj]);
                float lty = fmaxf(iy1, cy1[jj]);
                float rbx = fminf(ix2, cx2[jj]);
                float rby = fminf(iy2, cy2[jj]);
                float w = fmaxf(__fsub_rn(rbx, ltx), 0.0f);
                float h = fmaxf(__fsub_rn(rby, lty), 0.0f);
                float inter = __fmul_rn(w, h);
                float den = __fadd_rn(__fsub_rn(__fadd_rn(ai, car[jj]), inter), 1e-9f);
                if (__fdiv_rn(inter, den) > 0.7f) word |= (1ull << jj);
            }
        }
    }
    if (i < 1024) g_lmask[pair][i][colb] = word;  // zeros beyond kl keep eager ORs safe
}

// ================= per-level greedy NMS (40 independent blocks) =================
__global__ __launch_bounds__(64) void lnms_kernel() {
    int pair = blockIdx.x; int lvl = pair % 5;
    int kl = c_KLVL[lvl];
    int nc = (kl + 63) >> 6;
    int tid = threadIdx.x;
    __shared__ u64 remv[NWL];
    __shared__ u64 smask[64];
    __shared__ u64 kb[NWL];
    __shared__ int skept[64];
    __shared__ int snk;
    if (tid < NWL) { remv[tid] = 0ull; kb[tid] = 0ull; }
    __syncthreads();

    for (int c = 0; c < nc; c++) {
        int i0 = c * 64;
        { int i = i0 + tid; smask[tid] = (i < kl) ? g_lmask[pair][i][c] : 0ull; }
        __syncthreads();
        if (tid == 0) {
            u64 alive = g_lvb[pair][c] & ~remv[c];
            int nk = 0; u64 kw = 0ull;
            while (alive) {
                int b = __ffsll((long long)alive) - 1;
                skept[nk++] = i0 + b; kw |= (1ull << b);
                alive &= ~smask[b];              // row has only j>i bits
                alive &= ~(1ull << b);
            }
            snk = nk; kb[c] = kw;
        }
        __syncthreads();
        int nk = snk, nw = nc - 1 - c;
        int total = nk * nw;
        for (int p = tid; p < total; p += 64) {
            int kk = p / nw; int w = c + 1 + (p - kk * nw);
            u64 mm = g_lmask[pair][skept[kk]][w];
            if (mm) atomicOr(&remv[w], mm);
        }
        __syncthreads();
    }
    if (tid < NWL) g_keepbits[pair][tid] = kb[tid];
}

// ================= rank + merge kept + output (fused, per image) =================
__global__ __launch_bounds__(1024) void rankfin_kernel(float* __restrict__ out) {
    int img = blockIdx.x;
    int tid = threadIdx.x;
    int lane = tid & 31, warp = tid >> 5;

    __shared__ u64 levKeys[KSEL];
    __shared__ u32 sh_wsum[32];
    __shared__ u32 sh_levStart[6];
    __shared__ u32 sh_carry, sh_total;
    __shared__ u64 kbits[NWORDS];
    __shared__ u32 pref[NWORDS + 1];

    for (int t = tid; t < NWORDS; t += 1024) kbits[t] = 0ull;

    u64 key[5]; u32 gvp[5]; bool val[5];
    #pragma unroll
    for (int s = 0; s < 5; s++) {
        int p = s * 1024 + tid;
        key[s] = 0ull; val[s] = false;
        if (p < KSEL) {
            u64 kk = g_key[img][p];
            key[s] = kk;
            val[s] = ((u32)(kk >> 32)) >= 0x80000000u;   // sigmoid>0 vs -1
        }
    }
    if (tid == 0) sh_carry = 0;

    // block-wide exclusive scan of valid flags (pos order)
    #pragma unroll
    for (int s = 0; s < 5; s++) {
        int p = s * 1024 + tid;
        u32 bal = __ballot_sync(0xFFFFFFFFu, val[s]);
        u32 wpre = __popc(bal & ((1u << lane) - 1u));
        __syncthreads();
        if (lane == 0) sh_wsum[warp] = __popc(bal);
        __syncthreads();
        if (tid < 32) {
            u32 v = sh_wsum[tid];
            u32 x = v;
            #pragma unroll
            for (int o = 1; o < 32; o <<= 1) {
                u32 y = __shfl_up_sync(0xFFFFFFFFu, x, o);
                if (tid >= o) x += y;
            }
            sh_wsum[tid] = x - v;
            if (tid == 31) sh_total = x;
        }
        __syncthreads();
        gvp[s] = sh_carry + sh_wsum[warp] + wpre;
        if (p < KSEL && (p % 1000) == 0 && p < 5000) sh_levStart[p / 1000] = gvp[s];
        __syncthreads();
        if (tid == 0) sh_carry += sh_total;
    }
    __syncthreads();
    if (tid == 0) sh_levStart[5] = sh_carry;
    __syncthreads();

    #pragma unroll
    for (int s = 0; s < 5; s++) {
        int p = s * 1024 + tid;
        if (p < KSEL && val[s]) levKeys[gvp[s]] = key[s];
    }
    __syncthreads();
    u32 totalValid = sh_levStart[5];

    // global rank per pos + kept flags into kbits
    u32 rr[5]; bool kt[5];
    #pragma unroll
    for (int s = 0; s < 5; s++) {
        int p = s * 1024 + tid;
        rr[s] = 0; kt[s] = false;
        if (p >= KSEL) continue;
        int lvl = p / 1000; if (lvl > 4) lvl = 4;
        u32 r;
        if (val[s]) {
            r = gvp[s] - sh_levStart[lvl];
            #pragma unroll
            for (int l2 = 0; l2 < 5; l2++) {
                if (l2 == lvl) continue;
                u32 lo = sh_levStart[l2], hi = sh_levStart[l2 + 1];
                u32 st = lo;
                while (lo < hi) {
                    u32 mid = (lo + hi) >> 1;
                    if (levKeys[mid] > key[s]) lo = mid + 1; else hi = mid;
                }
                r += lo - st;
            }
            int li = p - c_SELOFF[lvl];
            bool kept = (g_keepbits[img * 5 + lvl][li >> 6] >> (li & 63)) & 1ull;
            if (kept) {
                atomicOr(&kbits[r >> 6], 1ull << (r & 63));
                kt[s] = true;
            }
        } else {
            r = totalValid + ((u32)p - gvp[s]);
        }
        rr[s] = r;
    }
    __syncthreads();
    if (tid == 0) {
        u32 s = 0;
        for (int w = 0; w < NWORDS; w++) { pref[w] = s; s += (u32)__popcll(kbits[w]); }
        pref[NWORDS] = s;
    }
    __syncthreads();

    #pragma unroll
    for (int s = 0; s < 5; s++) {
        int p = s * 1024 + tid;
        if (p >= KSEL || !kt[s]) continue;
        u32 r = rr[s];
        u32 low = (r & 63) ? (u32)__popcll(kbits[r >> 6] & ((1ull << (r & 63)) - 1ull)) : 0u;
        u32 orank = pref[r >> 6] + low;
        if (orank < POSTN) {
            float4 b = g_px[img][p];
            float* o = out + ((size_t)img * POSTN + orank) * 4;
            o[0] = b.x; o[1] = b.y; o[2] = b.z; o[3] = b.w;
        }
    }
    int tot = (int)pref[NWORDS]; if (tot > POSTN) tot = POSTN;
    for (int idx = tot * 4 + tid; idx < POSTN * 4; idx += 1024)
        out[(size_t)img * POSTN * 4 + idx] = 0.0f;
}

// ================= host launcher =================
extern "C" void kernel_launch(void* const* d_in, const int* in_sizes, int n_in,
                              void* d_out, int out_size) {
    KArgs A;
    bool interleaved = (in_sizes[1] == 6291456);
    for (int i = 0; i < 5; i++) {
        A.obj[i] = (const float*)d_in[interleaved ? 2 * i : i];
        A.del[i] = (const float*)d_in[interleaved ? 2 * i + 1 : 5 + i];
    }
    A.anc = (const float*)d_in[10];
    float* out = (float*)d_out;

    histA_kernel<<<dim3(40, 16), 256>>>(A);
    cut_kernel<<<1, 256>>>();
    compact_kernel<<<dim3(40, 16), 256>>>(A);
    selfin_kernel<<<40, 1024>>>();
    decode_kernel<<<dim3(19, NIMG), 256>>>(A);
    lmask_kernel<<<dim3(NWL, 4, 40), 256>>>();
    lnms_kernel<<<40, 64>>>();
    rankfin_kernel<<<NIMG, 1024>>>(out);
}

// round 12
// speedup vs baseline: 1.7261x; 1.1712x over previous
#include <cuda_runtime.h>
#include <math.h>
#include <stdint.h>

#define NIMG   8
#define KSEL   4768
#define NWORDS 75          /* ceil(4768/64) global-rank words */
#define NWL    16          /* per-level mask words (1024/64) */
#define POSTN  1000
#define CANDCAP 16384

typedef unsigned long long u64;
typedef unsigned int u32;

__device__ __constant__ int c_FEAT[5]   = {256, 128, 64, 32, 16};
__device__ __constant__ int c_KLVL[5]   = {1000, 1000, 1000, 1000, 768};
__device__ __constant__ int c_SELOFF[5] = {0, 1000, 2000, 3000, 4000};
__device__ __constant__ int c_LOFF[5]   = {0, 196608, 245760, 258048, 261120};

struct KArgs {
    const float* obj[5];
    const float* del[5];
    const float* anc;
};

// ------------- static device scratch (no allocation) -------------
__device__ u32    g_hist[40][256];             // radix histograms (re-zeroed by cut)
__device__ u32    g_d1[40], g_kr0[40], g_cntC[40];
__device__ u64    g_cand[40][CANDCAP];         // sel candidate scratch
__device__ u64    g_key[NIMG][KSEL];           // composite sort keys (pos-indexed)
__device__ float4 g_px[NIMG][KSEL];            // pos-indexed clipped boxes
// per-(img,lvl) level-local offset boxes / area / validity / keep bits
__device__ float  g_lx1[40][1024], g_ly1[40][1024], g_lx2[40][1024], g_ly2[40][1024];
__device__ float  g_lar[40][1024];
__device__ u64    g_lvb[40][NWL];              // valid bits (zeroed by cut)
__device__ u64    g_keepbits[40][NWL];         // NMS keep flags per level
__device__ u64    g_lmask[40][1024][NWL];      // per-level suppression matrix

// monotone float->uint key (ascending float == ascending uint)
__device__ __forceinline__ u32 fkey(float f) {
    u32 b = __float_as_uint(f);
    return (b & 0x80000000u) ? ~b : (b | 0x80000000u);
}
// exact inverse of fkey
__device__ __forceinline__ float fkey_inv(u32 k) {
    return (k & 0x80000000u) ? __uint_as_float(k & 0x7FFFFFFFu)
                             : __uint_as_float(~k);
}

// ================= sel stage A: chip-wide top-8-bit histogram =================
__global__ __launch_bounds__(256) void histA_kernel(KArgs A) {
    int pair = blockIdx.x; int img = pair / 5, lvl = pair % 5;
    int F = c_FEAT[lvl]; int HW = F * F; int n = HW * 3;
    const float* base = A.obj[lvl] + (size_t)img * 3 * HW;
    int lane = threadIdx.x & 31;
    __shared__ u32 h[256];
    h[threadIdx.x] = 0;
    __syncthreads();
    int stride = gridDim.y * 256;
    // n is a multiple of 256 per level => every executed iteration is full-warp
    for (int t = blockIdx.y * 256 + threadIdx.x; t < n; t += stride) {
        u32 d = fkey(base[t]) >> 24;
        u32 peers = __match_any_sync(0xFFFFFFFFu, d);
        if (lane == (__ffs(peers) - 1))
            atomicAdd(&h[d], (u32)__popc(peers));
    }
    __syncthreads();
    u32 v = h[threadIdx.x];
    if (v) atomicAdd(&g_hist[pair][threadIdx.x], v);
}

// ================= sel stage B: find cut bucket + re-zero per-replay state =================
__global__ __launch_bounds__(256) void cut_kernel() {
    int pair = threadIdx.x;
    if (pair < 40) {
        int lvl = pair % 5;
        u32 kr = (u32)c_KLVL[lvl], sum = 0; int d = 0;
        for (d = 255; d >= 0; d--) {
            u32 s2 = sum + g_hist[pair][d];
            if (s2 >= kr) { g_kr0[pair] = kr - sum; break; }
            sum = s2;
        }
        g_d1[pair] = (u32)d;
        g_cntC[pair] = 0;
    }
    __syncthreads();
    for (int t = threadIdx.x; t < 40 * 256; t += 256)
        ((u32*)g_hist)[t] = 0;                 // for next replay
    for (int t = threadIdx.x; t < 40 * NWL; t += 256)
        ((u64*)g_lvb)[t] = 0ull;               // selfin decode-tail ORs into this
}

// ================= sel stage C: chip-wide candidate compaction =================
__global__ __launch_bounds__(256) void compact_kernel(KArgs A) {
    int pair = blockIdx.x; int img = pair / 5, lvl = pair % 5;
    int F = c_FEAT[lvl]; int HW = F * F; int n = HW * 3;
    const float* base = A.obj[lvl] + (size_t)img * 3 * HW;
    u32 d1 = g_d1[pair];
    u64* cand = g_cand[pair];
    int lane = threadIdx.x & 31;
    int stride = gridDim.y * 256;
    for (int t = blockIdx.y * 256 + threadIdx.x; t < n; t += stride) {
        u32 key = fkey(base[t]);
        bool pred = ((key >> 24) >= d1);
        u32 bal = __ballot_sync(0xFFFFFFFFu, pred);
        u32 base_s = 0;
        if (bal) {
            int leader = __ffs(bal) - 1;
            if (lane == leader) base_s = atomicAdd(&g_cntC[pair], (u32)__popc(bal));
            base_s = __shfl_sync(0xFFFFFFFFu, base_s, leader);
        }
        if (pred) {
            u32 s = base_s + __popc(bal & ((1u << lane) - 1u));
            if (s < CANDCAP) {
                int a = t / HW; int hw = t - a * HW;
                u32 local = (u32)hw * 3u + (u32)a;     // [H,W,A] flatten index
                cand[s] = ((u64)key << 32) | (u32)(~local);
            }
        }
    }
}

// ===== sel stage D: radix 3-5 + dual-1024 bitonic + FUSED per-anchor decode =====
__global__ __launch_bounds__(1024) void selfin_kernel(KArgs A) {
    int pair = blockIdx.x; int img = pair / 5, lvl = pair % 5;
    int k = c_KLVL[lvl];
    u64* cand = g_cand[pair];
    u32 m = g_cntC[pair]; if (m > CANDCAP) m = CANDCAP;

    __shared__ u32 hist[256];
    __shared__ u32 sh_prefix, sh_kr;
    __shared__ u64 buf[2048];
    __shared__ u32 cntG, cntE;
    if (threadIdx.x == 0) {
        sh_prefix = g_d1[pair] << 24; sh_kr = g_kr0[pair];
        cntG = 0; cntE = 0;
    }
    __syncthreads();

    for (int b = 2; b >= 0; b--) {
        for (int t = threadIdx.x; t < 256; t += blockDim.x) hist[t] = 0;
        __syncthreads();
        u32 pref = sh_prefix;
        u32 maskH = 0xFFFFFFFFu << (8 * (b + 1));
        for (int t = threadIdx.x; t < (int)m; t += blockDim.x) {
            u32 key = (u32)(cand[t] >> 32);
            if ((key & maskH) == (pref & maskH))
                atomicAdd(&hist[(key >> (8 * b)) & 255u], 1u);
        }
        __syncthreads();
        if (threadIdx.x == 0) {
            u32 kr = sh_kr, sum = 0; int d = 0;
            for (d = 255; d >= 0; d--) {
                u32 s2 = sum + hist[d];
                if (s2 >= kr) { sh_kr = kr - sum; break; }
                sum = s2;
            }
            sh_prefix = pref | ((u32)d << (8 * b));
        }
        __syncthreads();
    }
    u32 Kth = sh_prefix;

    // compact: G (key > Kth, nG <= k-1 < 1024) into [0,1024); E (== Kth) into [1024,2048)
    for (int t = threadIdx.x; t < 2048; t += blockDim.x) buf[t] = 0ull;
    __syncthreads();
    for (int t = threadIdx.x; t < (int)m; t += blockDim.x) {
        u64 comp = cand[t];
        u32 key = (u32)(comp >> 32);
        if (key > Kth)       { u32 s = atomicAdd(&cntG, 1u); if (s < 1024u) buf[s] = comp; }
        else if (key == Kth) { u32 s = atomicAdd(&cntE, 1u); if (s < 1024u) buf[1024u + s] = comp; }
    }
    __syncthreads();

    // two independent descending 1024-bitonics (G half and E half); G > E blockwise
    for (int kk = 2; kk <= 1024; kk <<= 1)
        for (int j = kk >> 1; j > 0; j >>= 1) {
            __syncthreads();
            for (int t = threadIdx.x; t < 2048; t += 1024) {
                int ixj = t ^ j;
                if (ixj > t) {
                    u64 a = buf[t], bb = buf[ixj];
                    bool desc = (((t & 1023) & kk) == 0);
                    if (desc ? (a < bb) : (a > bb)) { buf[t] = bb; buf[ixj] = a; }
                }
            }
        }
    __syncthreads();
    u32 nG = cntG;   // exact count (< 1024 mathematically)

    // ---- fused decode: thread r handles rank r of this level ----
    int r = threadIdx.x;
    if (r < k) {
        u64 comp = (r < (int)nG) ? buf[r] : buf[1024 + (r - (int)nG)];
        u32 keyhi = (u32)(comp >> 32);
        u32 local = ~(u32)comp;
        int loff = c_LOFF[lvl]; int F = c_FEAT[lvl]; int HW = F * F;
        int a = (int)(local % 3u); int hw = (int)(local / 3u);
        int h = hw / F; int w = hw - h * F;
        u32 gidx = (u32)loff + local;
        int pos = c_SELOFF[lvl] + r;

        float logit = fkey_inv(keyhi);
        float score = __fdiv_rn(1.0f, __fadd_rn(1.0f, expf(-logit)));

        const float* dp = A.del[lvl] + ((size_t)img * 12 + a * 4) * HW + (size_t)h * F + w;
        float dx  = dp[0];
        float dy  = dp[(size_t)HW];
        float dwv = dp[2 * (size_t)HW];
        float dhv = dp[3 * (size_t)HW];
        const float* an = A.anc + 4 * (size_t)gidx;
        float ax1 = an[0], ay1 = an[1], ax2 = an[2], ay2 = an[3];
        float aw = __fsub_rn(ax2, ax1);
        float ah = __fsub_rn(ay2, ay1);
        float cx = __fadd_rn(ax1, __fmul_rn(0.5f, aw));
        float cy = __fadd_rn(ay1, __fmul_rn(0.5f, ah));
        const float CLIP = 4.135166556742356f;
        float dwc = fminf(dwv, CLIP);
        float dhc = fminf(dhv, CLIP);
        float pcx = __fadd_rn(__fmul_rn(dx, aw), cx);
        float pcy = __fadd_rn(__fmul_rn(dy, ah), cy);
        float pw  = __fmul_rn(expf(dwc), aw);
        float ph  = __fmul_rn(expf(dhc), ah);
        float x1 = __fsub_rn(pcx, __fmul_rn(0.5f, pw));
        float y1 = __fsub_rn(pcy, __fmul_rn(0.5f, ph));
        float x2 = __fadd_rn(pcx, __fmul_rn(0.5f, pw));
        float y2 = __fadd_rn(pcy, __fmul_rn(0.5f, ph));
        x1 = fminf(fmaxf(x1, 0.0f), 1024.0f);
        y1 = fminf(fmaxf(y1, 0.0f), 1024.0f);
        x2 = fminf(fmaxf(x2, 0.0f), 1024.0f);
        y2 = fminf(fmaxf(y2, 0.0f), 1024.0f);

        bool valid = (__fsub_rn(x2, x1) >= 1e-3f) && (__fsub_rn(y2, y1) >= 1e-3f);
        g_px[img][pos] = make_float4(x1, y1, x2, y2);
        float sc = valid ? score : -1.0f;
        g_key[img][pos] = ((u64)fkey(sc) << 32) | (u32)(~(u32)pos);

        float ofs = (float)lvl * 1025.0f;
        float ox1 = __fadd_rn(x1, ofs), oy1 = __fadd_rn(y1, ofs);
        float ox2 = __fadd_rn(x2, ofs), oy2 = __fadd_rn(y2, ofs);
        g_lx1[pair][r] = ox1; g_ly1[pair][r] = oy1;
        g_lx2[pair][r] = ox2; g_ly2[pair][r] = oy2;
        g_lar[pair][r] = __fmul_rn(__fsub_rn(ox2, ox1), __fsub_rn(oy2, oy1));
        if (valid) atomicOr(&g_lvb[pair][r >> 6], 1ull << (r & 63));
    }
}

// ================= per-level IoU suppression matrix (upper tri) =================
__global__ __launch_bounds__(256) void lmask_kernel() {
    int pair = blockIdx.z; int lvl = pair % 5;
    int kl = c_KLVL[lvl];
    int colb = blockIdx.x, rowb4 = blockIdx.y;
    if (rowb4 * 4 > colb) return;            // whole block lower triangle
    int tid = threadIdx.x;
    int sub = tid >> 6, lane = tid & 63;
    int rowb = rowb4 * 4 + sub;

    __shared__ float cx1[64], cy1[64], cx2[64], cy2[64], car[64];
    int j0 = colb * 64;
    if (tid < 64) {
        int j = j0 + tid;
        if (j < kl) {
            cx1[tid] = g_lx1[pair][j]; cy1[tid] = g_ly1[pair][j];
            cx2[tid] = g_lx2[pair][j]; cy2[tid] = g_ly2[pair][j];
            car[tid] = g_lar[pair][j];
        } else {
            cx1[tid] = 0.f; cy1[tid] = 0.f; cx2[tid] = 0.f; cy2[tid] = 0.f; car[tid] = 0.f;
        }
    }
    __syncthreads();
    if (rowb > colb) return;
    int i = rowb * 64 + lane;
    u64 word = 0ull;
    if (i < kl) {
        float ix1 = g_lx1[pair][i], iy1 = g_ly1[pair][i];
        float ix2 = g_lx2[pair][i], iy2 = g_ly2[pair][i];
        float ai = g_lar[pair][i];
        int jmax = kl - j0; if (jmax > 64) jmax = 64;
        #pragma unroll 8
        for (int jj = 0; jj < 64; jj++) {
            if (jj < jmax && j0 + jj > i) {
                float ltx = fmaxf(ix1, cx1[jj]);
                float lty = fmaxf(iy1, cy1[jj]);
                float rbx = fminf(ix2, cx2[jj]);
                float rby = fminf(iy2, cy2[jj]);
                float w = fmaxf(__fsub_rn(rbx, ltx), 0.0f);
                float h = fmaxf(__fsub_rn(rby, lty), 0.0f);
                float inter = __fmul_rn(w, h);
                float den = __fadd_rn(__fsub_rn(__fadd_rn(ai, car[jj]), inter), 1e-9f);
                // guarded exact-divide: margins >> rounding error of div.rn
                bool sup;
                if (inter > __fmul_rn(den, 0.703125f))       sup = true;
                else if (inter < __fmul_rn(den, 0.6953125f)) sup = false;
                else sup = (__fdiv_rn(inter, den) > 0.7f);
                if (sup) word |= (1ull << jj);
            }
        }
    }
    if (i < 1024) g_lmask[pair][i][colb] = word;  // zeros beyond kl keep eager ORs safe
}

// ================= per-level greedy NMS (40 independent blocks) =================
__global__ __launch_bounds__(64) void lnms_kernel() {
    int pair = blockIdx.x; int lvl = pair % 5;
    int kl = c_KLVL[lvl];
    int nc = (kl + 63) >> 6;
    int tid = threadIdx.x;
    __shared__ u64 remv[NWL];
    __shared__ u64 smask[64];
    __shared__ u64 kb[NWL];
    __shared__ int skept[64];
    __shared__ int snk;
    if (tid < NWL) { remv[tid] = 0ull; kb[tid] = 0ull; }
    __syncthreads();

    for (int c = 0; c < nc; c++) {
        int i0 = c * 64;
        { int i = i0 + tid; smask[tid] = (i < kl) ? g_lmask[pair][i][c] : 0ull; }
        __syncthreads();
        if (tid == 0) {
            u64 alive = g_lvb[pair][c] & ~remv[c];
            int nk = 0; u64 kw = 0ull;
            while (alive) {
                int b = __ffsll((long long)alive) - 1;
                skept[nk++] = i0 + b; kw |= (1ull << b);
                alive &= ~smask[b];              // row has only j>i bits
                alive &= ~(1ull << b);
            }
            snk = nk; kb[c] = kw;
        }
        __syncthreads();
        int nk = snk, nw = nc - 1 - c;
        int total = nk * nw;
        for (int p = tid; p < total; p += 64) {
            int kk = p / nw; int w = c + 1 + (p - kk * nw);
            u64 mm = g_lmask[pair][skept[kk]][w];
            if (mm) atomicOr(&remv[w], mm);
        }
        __syncthreads();
    }
    if (tid < NWL) g_keepbits[pair][tid] = kb[tid];
}

// ================= rank + merge kept + output (fused, per image) =================
__global__ __launch_bounds__(1024) void rankfin_kernel(float* __restrict__ out) {
    int img = blockIdx.x;
    int tid = threadIdx.x;
    int lane = tid & 31, warp = tid >> 5;

    __shared__ u64 levKeys[KSEL];
    __shared__ u32 sh_wsum[32];
    __shared__ u32 sh_levStart[6];
    __shared__ u32 sh_carry, sh_total;
    __shared__ u64 kbits[NWORDS];
    __shared__ u32 pref[NWORDS + 1];

    for (int t = tid; t < NWORDS; t += 1024) kbits[t] = 0ull;

    u64 key[5]; u32 gvp[5]; bool val[5];
    #pragma unroll
    for (int s = 0; s < 5; s++) {
        int p = s * 1024 + tid;
        key[s] = 0ull; val[s] = false;
        if (p < KSEL) {
            u64 kk = g_key[img][p];
            key[s] = kk;
            val[s] = ((u32)(kk >> 32)) >= 0x80000000u;   // sigmoid>0 vs -1
        }
    }
    if (tid == 0) sh_carry = 0;

    // block-wide exclusive scan of valid flags (pos order)
    #pragma unroll
    for (int s = 0; s < 5; s++) {
        int p = s * 1024 + tid;
        u32 bal = __ballot_sync(0xFFFFFFFFu, val[s]);
        u32 wpre = __popc(bal & ((1u << lane) - 1u));
        __syncthreads();
        if (lane == 0) sh_wsum[warp] = __popc(bal);
        __syncthreads();
        if (tid < 32) {
            u32 v = sh_wsum[tid];
            u32 x = v;
            #pragma unroll
            for (int o = 1; o < 32; o <<= 1) {
                u32 y = __shfl_up_sync(0xFFFFFFFFu, x, o);
                if (tid >= o) x += y;
            }
            sh_wsum[tid] = x - v;
            if (tid == 31) sh_total = x;
        }
        __syncthreads();
        gvp[s] = sh_carry + sh_wsum[warp] + wpre;
        if (p < KSEL && (p % 1000) == 0 && p < 5000) sh_levStart[p / 1000] = gvp[s];
        __syncthreads();
        if (tid == 0) sh_carry += sh_total;
    }
    __syncthreads();
    if (tid == 0) sh_levStart[5] = sh_carry;
    __syncthreads();

    #pragma unroll
    for (int s = 0; s < 5; s++) {
        int p = s * 1024 + tid;
        if (p < KSEL && val[s]) levKeys[gvp[s]] = key[s];
    }
    __syncthreads();
    u32 totalValid = sh_levStart[5];

    // global rank per pos + kept flags into kbits
    u32 rr[5]; bool kt[5];
    #pragma unroll
    for (int s = 0; s < 5; s++) {
        int p = s * 1024 + tid;
        rr[s] = 0; kt[s] = false;
        if (p >= KSEL) continue;
        int lvl = p / 1000; if (lvl > 4) lvl = 4;
        u32 r;
        if (val[s]) {
            r = gvp[s] - sh_levStart[lvl];
            #pragma unroll
            for (int l2 = 0; l2 < 5; l2++) {
                if (l2 == lvl) continue;
                u32 lo = sh_levStart[l2], hi = sh_levStart[l2 + 1];
                u32 st = lo;
                while (lo < hi) {
                    u32 mid = (lo + hi) >> 1;
                    if (levKeys[mid] > key[s]) lo = mid + 1; else hi = mid;
                }
                r += lo - st;
            }
            int li = p - c_SELOFF[lvl];
            bool kept = (g_keepbits[img * 5 + lvl][li >> 6] >> (li & 63)) & 1ull;
            if (kept) {
                atomicOr(&kbits[r >> 6], 1ull << (r & 63));
                kt[s] = true;
            }
        } else {
            r = totalValid + ((u32)p - gvp[s]);
        }
        rr[s] = r;
    }
    __syncthreads();
    if (tid == 0) {
        u32 s = 0;
        for (int w = 0; w < NWORDS; w++) { pref[w] = s; s += (u32)__popcll(kbits[w]); }
        pref[NWORDS] = s;
    }
    __syncthreads();

    #pragma unroll
    for (int s = 0; s < 5; s++) {
        int p = s * 1024 + tid;
        if (p >= KSEL || !kt[s]) continue;
        u32 r = rr[s];
        u32 low = (r & 63) ? (u32)__popcll(kbits[r >> 6] & ((1ull << (r & 63)) - 1ull)) : 0u;
        u32 orank = pref[r >> 6] + low;
        if (orank < POSTN) {
            float4 b = g_px[img][p];
            float* o = out + ((size_t)img * POSTN + orank) * 4;
            o[0] = b.x; o[1] = b.y; o[2] = b.z; o[3] = b.w;
        }
    }
    int tot = (int)pref[NWORDS]; if (tot > POSTN) tot = POSTN;
    for (int idx = tot * 4 + tid; idx < POSTN * 4; idx += 1024)
        out[(size_t)img * POSTN * 4 + idx] = 0.0f;
}

// ================= host launcher =================
extern "C" void kernel_launch(void* const* d_in, const int* in_sizes, int n_in,
                              void* d_out, int out_size) {
    KArgs A;
    bool interleaved = (in_sizes[1] == 6291456);
    for (int i = 0; i < 5; i++) {
        A.obj[i] = (const float*)d_in[interleaved ? 2 * i : i];
        A.del[i] = (const float*)d_in[interleaved ? 2 * i + 1 : 5 + i];
    }
    A.anc = (const float*)d_in[10];
    float* out = (float*)d_out;

    histA_kernel<<<dim3(40, 16), 256>>>(A);
    cut_kernel<<<1, 256>>>();
    compact_kernel<<<dim3(40, 16), 256>>>(A);
    selfin_kernel<<<40, 1024>>>(A);
    lmask_kernel<<<dim3(NWL, 4, 40), 256>>>();
    lnms_kernel<<<40, 64>>>();
    rankfin_kernel<<<NIMG, 1024>>>(out);
}